// round 13
// baseline (speedup 1.0000x reference)
#include <cuda_runtime.h>
#include <cuda_bf16.h>
#include <cstdint>

#define N_NODES 10000
#define N_EDGES 640000
#define D 128
#define CAPR 64            // per-replica bucket capacity (mean 16, 4 replicas)
#define CAP 256            // total bucket stride = 4 * CAPR
#define FILL_BLOCKS 313    // ceil(640000/8/256)
#define CVT_BLOCKS 1250    // 10000*32/256
#define GEMM_BLOCKS 79     // ceil(10000/128)

// ---------------- scratch (device globals; no allocation allowed) ----------
__device__ float g_agg[N_NODES * D];
__device__ uint2 g_xh[N_NODES * 32];  // x in packed bf16
__device__ float4 g_vself[N_NODES];   // (A1 , A3) self terms
__device__ float4 g_vnb[N_NODES];     // (A2 , A4) neighbor terms
__device__ float2 g_ps[N_NODES];
__device__ float2 g_pd[N_NODES];
__device__ float g_wc[D * 8];         // [A1|A2|A3|A4] rows
__device__ float g_c[4];
__device__ int g_cnt[N_NODES * 4];    // 4 replicated counters/node; zeroed in k_agg2
__device__ int g_csr[N_NODES * CAP];

// ---------------- helpers ---------------------------------------------------
__device__ __forceinline__ uint32_t f2tf32(float v) {
    uint32_t t;
    asm("cvt.rna.tf32.f32 %0, %1;" : "=r"(t) : "f"(v));
    return t;
}
__device__ __forceinline__ void mma_tf32(float* c, const uint32_t* a,
                                         uint32_t b0, uint32_t b1) {
    asm volatile(
        "mma.sync.aligned.m16n8k8.row.col.f32.tf32.tf32.f32 "
        "{%0,%1,%2,%3}, {%4,%5,%6,%7}, {%8,%9}, {%0,%1,%2,%3};"
        : "+f"(c[0]), "+f"(c[1]), "+f"(c[2]), "+f"(c[3])
        : "r"(a[0]), "r"(a[1]), "r"(a[2]), "r"(a[3]), "r"(b0), "r"(b1));
}

// ---------------- fused prep: CSR fill + bf16 convert + weight fold --------
__global__ void k_prep(const int* __restrict__ src, const int* __restrict__ dst,
                       const float* __restrict__ x,
                       const float* __restrict__ Ws2,
                       const float* __restrict__ Wn2,
                       const float* __restrict__ b2,
                       const float* __restrict__ Wp) {
    __shared__ float sWp[256 * 2];
    int b = blockIdx.x;
    int tid = threadIdx.x;
    if (b < FILL_BLOCKS) {
        int t = b * 256 + tid;
        if (t * 8 >= N_EDGES) return;
        int r = tid & 3;   // counter replica for this thread's edges
        int4 s0 = ((const int4*)src)[2 * t], s1 = ((const int4*)src)[2 * t + 1];
        int4 d0 = ((const int4*)dst)[2 * t], d1 = ((const int4*)dst)[2 * t + 1];
        int p0 = atomicAdd(&g_cnt[d0.x * 4 + r], 1);
        int p1 = atomicAdd(&g_cnt[d0.y * 4 + r], 1);
        int p2 = atomicAdd(&g_cnt[d0.z * 4 + r], 1);
        int p3 = atomicAdd(&g_cnt[d0.w * 4 + r], 1);
        int p4 = atomicAdd(&g_cnt[d1.x * 4 + r], 1);
        int p5 = atomicAdd(&g_cnt[d1.y * 4 + r], 1);
        int p6 = atomicAdd(&g_cnt[d1.z * 4 + r], 1);
        int p7 = atomicAdd(&g_cnt[d1.w * 4 + r], 1);
        int rb = r * CAPR;
        if (p0 < CAPR) g_csr[d0.x * CAP + rb + p0] = s0.x;
        if (p1 < CAPR) g_csr[d0.y * CAP + rb + p1] = s0.y;
        if (p2 < CAPR) g_csr[d0.z * CAP + rb + p2] = s0.z;
        if (p3 < CAPR) g_csr[d0.w * CAP + rb + p3] = s0.w;
        if (p4 < CAPR) g_csr[d1.x * CAP + rb + p4] = s1.x;
        if (p5 < CAPR) g_csr[d1.y * CAP + rb + p5] = s1.y;
        if (p6 < CAPR) g_csr[d1.z * CAP + rb + p6] = s1.z;
        if (p7 < CAPR) g_csr[d1.w * CAP + rb + p7] = s1.w;
    } else if (b < FILL_BLOCKS + CVT_BLOCKS) {
        int idx = (b - FILL_BLOCKS) * 256 + tid;
        if (idx >= N_NODES * 32) return;
        float4 v = ((const float4*)x)[idx];
        __nv_bfloat162 q0 = __floats2bfloat162_rn(v.x, v.y);
        __nv_bfloat162 q1 = __floats2bfloat162_rn(v.z, v.w);
        uint2 u;
        u.x = *reinterpret_cast<unsigned*>(&q0);
        u.y = *reinterpret_cast<unsigned*>(&q1);
        g_xh[idx] = u;
    } else {
        for (int i = tid; i < 512; i += 256) sWp[i] = Wp[i];
        __syncthreads();
        int t = tid;
        if (t < 128) {
            float a[8] = {0, 0, 0, 0, 0, 0, 0, 0};
#pragma unroll 4
            for (int j = 0; j < D; j++) {
                float ws = Ws2[t * D + j];
                float wn = Wn2[t * D + j];
                float p0 = sWp[j * 2], p1 = sWp[j * 2 + 1];
                float q0 = sWp[(128 + j) * 2], q1 = sWp[(128 + j) * 2 + 1];
                a[0] += ws * p0; a[1] += ws * p1;
                a[2] += wn * p0; a[3] += wn * p1;
                a[4] += ws * q0; a[5] += ws * q1;
                a[6] += wn * q0; a[7] += wn * q1;
            }
#pragma unroll
            for (int j = 0; j < 8; j++) g_wc[t * 8 + j] = a[j];
        }
        if (t < 4) {
            int half = t >> 1, c = t & 1;
            float s = 0.f;
            for (int j = 0; j < D; j++)
                s += b2[j] * sWp[(half * 128 + j) * 2 + c];
            g_c[t] = s;
        }
    }
}

// ---------------- pull-based mean aggregation over bf16 x ------------------
__global__ void k_agg(const float* __restrict__ unused) {
    cudaGridDependencySynchronize();   // needs g_cnt/g_csr/g_xh from prep
    cudaTriggerProgrammaticLaunchCompletion();  // let k_layer_mma start now
    int gid = blockIdx.x * blockDim.x + threadIdx.x;
    int n = gid >> 5;
    int lane = gid & 31;
    if (n >= N_NODES) return;
    int4 c4 = ((const int4*)g_cnt)[n];
    int cnt_r[4] = {c4.x, c4.y, c4.z, c4.w};
    int d = c4.x + c4.y + c4.z + c4.w;
    float ax = 0.f, ay = 0.f, az = 0.f, aw = 0.f;
#pragma unroll
    for (int r = 0; r < 4; r++) {
        int cr = cnt_r[r];
        int beg = n * CAP + r * CAPR;
        for (int base = 0; base < cr; base += 32) {
            int my = -1;
            if (base + lane < cr) my = g_csr[beg + base + lane];
            int cnt = min(32, cr - base);
            int j = 0;
            for (; j + 8 <= cnt; j += 8) {
                int ss[8];
#pragma unroll
                for (int q = 0; q < 8; q++)
                    ss[q] = __shfl_sync(0xffffffffu, my, j + q);
                uint2 u[8];
#pragma unroll
                for (int q = 0; q < 8; q++) u[q] = g_xh[ss[q] * 32 + lane];
#pragma unroll
                for (int q = 0; q < 8; q++) {
                    float2 f;
                    f = __bfloat1622float2(
                        *reinterpret_cast<__nv_bfloat162*>(&u[q].x));
                    ax += f.x; ay += f.y;
                    f = __bfloat1622float2(
                        *reinterpret_cast<__nv_bfloat162*>(&u[q].y));
                    az += f.x; aw += f.y;
                }
            }
            for (; j < cnt; j++) {
                int s0 = __shfl_sync(0xffffffffu, my, j);
                uint2 u0 = g_xh[s0 * 32 + lane];
                float2 f;
                f = __bfloat1622float2(
                    *reinterpret_cast<__nv_bfloat162*>(&u0.x));
                ax += f.x; ay += f.y;
                f = __bfloat1622float2(
                    *reinterpret_cast<__nv_bfloat162*>(&u0.y));
                az += f.x; aw += f.y;
            }
        }
    }
    float inv = 1.0f / (float)(d < 1 ? 1 : d);
    float4 r;
    r.x = ax * inv; r.y = ay * inv; r.z = az * inv; r.w = aw * inv;
    *(float4*)(g_agg + (size_t)n * D + lane * 4) = r;
}

// -------- mma.sync tf32 layer 1 + fused projection -------------------------
#define ASTR 132   // 128 + 4 pad (u32 units)

__global__ void __launch_bounds__(256, 1)
k_layer_mma(const float* __restrict__ x, const float* __restrict__ agg,
            const float* __restrict__ Wself, const float* __restrict__ Wneigh,
            const float* __restrict__ bias) {
    // let k_agg2 launch immediately (its preload only needs prep outputs,
    // which were complete before this kernel launched)
    cudaTriggerProgrammaticLaunchCompletion();

    extern __shared__ uint32_t smu[];
    uint32_t* sA = smu;
    uint32_t* sB = smu + 128 * ASTR;
    float* sWc = (float*)(smu + 2 * 128 * ASTR);
    float* sBias = sWc + 1024;

    int tid = threadIdx.x;
    int wid = tid >> 5;
    int lane = tid & 31;
    int nb = blockIdx.x * 128;
    int valid = min(128, N_NODES - nb);

    // prologue: x, Wself, bias, wc — complete when agg's trigger fired
    for (int it = tid; it < 128 * 32; it += 256) {
        int r = it >> 5, q = it & 31;
        float4 vx = make_float4(0.f, 0.f, 0.f, 0.f);
        if (r < valid) vx = ((const float4*)x)[(size_t)(nb + r) * 32 + q];
        uint32_t* a = sA + r * ASTR + q * 4;
        a[0] = f2tf32(vx.x); a[1] = f2tf32(vx.y);
        a[2] = f2tf32(vx.z); a[3] = f2tf32(vx.w);
        float4 w = ((const float4*)Wself)[it];
        uint32_t* bp = sB + r * ASTR + q * 4;
        bp[0] = f2tf32(w.x); bp[1] = f2tf32(w.y);
        bp[2] = f2tf32(w.z); bp[3] = f2tf32(w.w);
    }
    for (int i = tid; i < D * 2; i += 256)
        ((float4*)sWc)[i] = ((const float4*)g_wc)[i];
    if (tid < 32) ((float4*)sBias)[tid] = ((const float4*)bias)[tid];
    __syncthreads();

    int wm = wid & 3, wn = wid >> 2;
    int tg8 = lane >> 2, tq = lane & 3;

    float c[2][8][4];
#pragma unroll
    for (int mi = 0; mi < 2; mi++)
#pragma unroll
        for (int ni = 0; ni < 8; ni++)
#pragma unroll
            for (int k = 0; k < 4; k++) c[mi][ni][k] = 0.f;

    // ---- pass 0: C = X @ Ws (overlaps k_agg) ----
#pragma unroll 2
    for (int kc = 0; kc < 16; kc++) {
        int k0 = kc * 8;
        uint32_t a[2][4];
#pragma unroll
        for (int mi = 0; mi < 2; mi++) {
            int row = 32 * wm + 16 * mi + tg8;
            a[mi][0] = sA[row * ASTR + k0 + tq];
            a[mi][1] = sA[(row + 8) * ASTR + k0 + tq];
            a[mi][2] = sA[row * ASTR + k0 + tq + 4];
            a[mi][3] = sA[(row + 8) * ASTR + k0 + tq + 4];
        }
#pragma unroll
        for (int ni = 0; ni < 8; ni++) {
            int col = 64 * wn + 8 * ni + tg8;
            uint32_t b0 = sB[(k0 + tq) * ASTR + col];
            uint32_t b1r = sB[(k0 + tq + 4) * ASTR + col];
            mma_tf32(c[0][ni], a[0], b0, b1r);
            mma_tf32(c[1][ni], a[1], b0, b1r);
        }
    }
    __syncthreads();

    cudaGridDependencySynchronize();   // wait for k_agg completion (g_agg)

    // ---- load pass 1 tiles: A = agg rows, B = Wneigh ----
    for (int it = tid; it < 128 * 32; it += 256) {
        int r = it >> 5, q = it & 31;
        float4 vm = make_float4(0.f, 0.f, 0.f, 0.f);
        if (r < valid)
            vm = ((const float4*)agg)[(size_t)(nb + r) * 32 + q];
        uint32_t* a = sA + r * ASTR + q * 4;
        a[0] = f2tf32(vm.x); a[1] = f2tf32(vm.y);
        a[2] = f2tf32(vm.z); a[3] = f2tf32(vm.w);
        float4 w = ((const float4*)Wneigh)[it];
        uint32_t* bp = sB + r * ASTR + q * 4;
        bp[0] = f2tf32(w.x); bp[1] = f2tf32(w.y);
        bp[2] = f2tf32(w.z); bp[3] = f2tf32(w.w);
    }
    __syncthreads();

    // ---- pass 1: C += M @ Wn ----
#pragma unroll 2
    for (int kc = 0; kc < 16; kc++) {
        int k0 = kc * 8;
        uint32_t a[2][4];
#pragma unroll
        for (int mi = 0; mi < 2; mi++) {
            int row = 32 * wm + 16 * mi + tg8;
            a[mi][0] = sA[row * ASTR + k0 + tq];
            a[mi][1] = sA[(row + 8) * ASTR + k0 + tq];
            a[mi][2] = sA[row * ASTR + k0 + tq + 4];
            a[mi][3] = sA[(row + 8) * ASTR + k0 + tq + 4];
        }
#pragma unroll
        for (int ni = 0; ni < 8; ni++) {
            int col = 64 * wn + 8 * ni + tg8;
            uint32_t b0 = sB[(k0 + tq) * ASTR + col];
            uint32_t b1r = sB[(k0 + tq + 4) * ASTR + col];
            mma_tf32(c[0][ni], a[0], b0, b1r);
            mma_tf32(c[1][ni], a[1], b0, b1r);
        }
    }

    __syncthreads();
    float* sH = (float*)sA;
#pragma unroll
    for (int mi = 0; mi < 2; mi++) {
        int r0 = 32 * wm + 16 * mi + tg8;
#pragma unroll
        for (int ni = 0; ni < 8; ni++) {
            int cb = 64 * wn + 8 * ni + 2 * tq;
            sH[r0 * ASTR + cb] = fmaxf(c[mi][ni][0] + sBias[cb], 0.f);
            sH[r0 * ASTR + cb + 1] = fmaxf(c[mi][ni][1] + sBias[cb + 1], 0.f);
            sH[(r0 + 8) * ASTR + cb] = fmaxf(c[mi][ni][2] + sBias[cb], 0.f);
            sH[(r0 + 8) * ASTR + cb + 1] =
                fmaxf(c[mi][ni][3] + sBias[cb + 1], 0.f);
        }
    }
    __syncthreads();

    int node = tid >> 1;
    int half = tid & 1;
    float pv[8] = {0, 0, 0, 0, 0, 0, 0, 0};
    const float* hrow = sH + node * ASTR + half * 64;
#pragma unroll 8
    for (int j = 0; j < 64; j++) {
        float h = hrow[j];
        int col = half * 64 + j;
        float4 w0 = *(const float4*)(sWc + col * 8);
        float4 w1 = *(const float4*)(sWc + col * 8 + 4);
        pv[0] += h * w0.x; pv[1] += h * w0.y;
        pv[2] += h * w0.z; pv[3] += h * w0.w;
        pv[4] += h * w1.x; pv[5] += h * w1.y;
        pv[6] += h * w1.z; pv[7] += h * w1.w;
    }
#pragma unroll
    for (int m = 0; m < 8; m++)
        pv[m] += __shfl_xor_sync(0xffffffffu, pv[m], 1);
    int gn = nb + node;
    if (half == 0 && gn < N_NODES) {
        g_vself[gn] = make_float4(pv[0], pv[1], pv[4], pv[5]);
        g_vnb[gn] = make_float4(pv[2], pv[3], pv[6], pv[7]);
    }
}

// ---------------- tiny aggregation: 8 lanes per node -----------------------
// Launched early (layer's trigger); preloads CSR indices before the sync so
// the gather setup overlaps the layer's MMA.
__global__ void k_agg2() {
    cudaTriggerProgrammaticLaunchCompletion();  // let k_edge start now
    int gid = blockIdx.x * blockDim.x + threadIdx.x;
    int n = gid >> 3;
    int sub = gid & 7;
    int4 c4 = make_int4(0, 0, 0, 0);
    if (n < N_NODES) c4 = ((const int4*)g_cnt)[n];
    int cnt_r[4] = {c4.x, c4.y, c4.z, c4.w};
    int d = c4.x + c4.y + c4.z + c4.w;
    // preload indices (mean 8 per lane across 4 replica segments)
    int idx[16];
    int nidx = 0;
#pragma unroll
    for (int r = 0; r < 4; r++) {
        int beg = n * CAP + r * CAPR;
        for (int i = sub; i < cnt_r[r] && nidx < 16; i += 8)
            idx[nidx++] = g_csr[beg + i];
    }

    cudaGridDependencySynchronize();   // needs g_vnb/g_vself from layer

    float ax = 0.f, ay = 0.f, az = 0.f, aw = 0.f;
    for (int i = 0; i < nidx; i++) {
        float4 v = g_vnb[idx[i]];
        ax += v.x; ay += v.y; az += v.z; aw += v.w;
    }
    // rare overflow tail (>16 slots for this lane in a replica pattern)
    {
        int seen = 0;
#pragma unroll
        for (int r = 0; r < 4; r++) {
            int beg = n * CAP + r * CAPR;
            for (int i = sub; i < cnt_r[r]; i += 8) {
                if (seen >= 16) {
                    int s = g_csr[beg + i];
                    float4 v = g_vnb[s];
                    ax += v.x; ay += v.y; az += v.z; aw += v.w;
                }
                seen++;
            }
        }
    }
#pragma unroll
    for (int off = 4; off > 0; off >>= 1) {
        ax += __shfl_xor_sync(0xffffffffu, ax, off);
        ay += __shfl_xor_sync(0xffffffffu, ay, off);
        az += __shfl_xor_sync(0xffffffffu, az, off);
        aw += __shfl_xor_sync(0xffffffffu, aw, off);
    }
    if (sub == 0 && n < N_NODES) {
        float inv = 1.0f / (float)(d < 1 ? 1 : d);
        float4 vs = g_vself[n];
        g_ps[n] = make_float2(vs.x + ax * inv, vs.y + ay * inv);
        g_pd[n] = make_float2(vs.z + az * inv, vs.w + aw * inv);
        ((int4*)g_cnt)[n] = make_int4(0, 0, 0, 0);  // replay invariant
    }
}

// ---------------- edge scores: 8 edges per thread --------------------------
__global__ void k_edge(const int* __restrict__ src, const int* __restrict__ dst,
                       const float* __restrict__ bpred,
                       float* __restrict__ out) {
    int t = blockIdx.x * blockDim.x + threadIdx.x;
    if (t * 8 >= N_EDGES) return;
    int4 s0 = ((const int4*)src)[2 * t], s1 = ((const int4*)src)[2 * t + 1];
    int4 d0 = ((const int4*)dst)[2 * t], d1 = ((const int4*)dst)[2 * t + 1];
    float b0 = __ldg(bpred) + g_c[0] + g_c[2];
    float b1v = __ldg(bpred + 1) + g_c[1] + g_c[3];

    cudaGridDependencySynchronize();   // needs g_ps/g_pd from agg2

    float2 a0 = g_ps[s0.x], a1 = g_ps[s0.y], a2 = g_ps[s0.z], a3 = g_ps[s0.w];
    float2 a4 = g_ps[s1.x], a5 = g_ps[s1.y], a6 = g_ps[s1.z], a7 = g_ps[s1.w];
    float2 c0 = g_pd[d0.x], c1 = g_pd[d0.y], c2 = g_pd[d0.z], c3 = g_pd[d0.w];
    float2 c4 = g_pd[d1.x], c5 = g_pd[d1.y], c6 = g_pd[d1.z], c7 = g_pd[d1.w];
    float4 o;
    o = make_float4(a0.x + c0.x + b0, a0.y + c0.y + b1v,
                    a1.x + c1.x + b0, a1.y + c1.y + b1v);
    ((float4*)out)[t * 4] = o;
    o = make_float4(a2.x + c2.x + b0, a2.y + c2.y + b1v,
                    a3.x + c3.x + b0, a3.y + c3.y + b1v);
    ((float4*)out)[t * 4 + 1] = o;
    o = make_float4(a4.x + c4.x + b0, a4.y + c4.y + b1v,
                    a5.x + c5.x + b0, a5.y + c5.y + b1v);
    ((float4*)out)[t * 4 + 2] = o;
    o = make_float4(a6.x + c6.x + b0, a6.y + c6.y + b1v,
                    a7.x + c7.x + b0, a7.y + c7.y + b1v);
    ((float4*)out)[t * 4 + 3] = o;
}

// ---------------- launcher (PDL-chained) ------------------------------------
static void launch_pdl(const void* func, dim3 grid, dim3 block, size_t smem,
                       void** args) {
    cudaLaunchConfig_t cfg = {};
    cfg.gridDim = grid;
    cfg.blockDim = block;
    cfg.dynamicSmemBytes = smem;
    cfg.stream = 0;
    cudaLaunchAttribute attr;
    attr.id = cudaLaunchAttributeProgrammaticStreamSerialization;
    attr.val.programmaticStreamSerializationAllowed = 1;
    cfg.attrs = &attr;
    cfg.numAttrs = 1;
    cudaLaunchKernelExC(&cfg, func, args);
}

extern "C" void kernel_launch(void* const* d_in, const int* in_sizes, int n_in,
                              void* d_out, int out_size) {
    const float* x = (const float*)d_in[0];
    const int* src = (const int*)d_in[1];
    const int* dst = (const int*)d_in[2];
    const float* Wself1 = (const float*)d_in[3];
    const float* Wneigh1 = (const float*)d_in[4];
    const float* b1 = (const float*)d_in[5];
    const float* Wself2 = (const float*)d_in[6];
    const float* Wneigh2 = (const float*)d_in[7];
    const float* b2 = (const float*)d_in[8];
    const float* Wpred = (const float*)d_in[9];
    const float* bpred = (const float*)d_in[10];
    float* out = (float*)d_out;

    size_t layer_smem = (size_t)(2 * 128 * ASTR + 1024 + 128) * 4;
    cudaFuncSetAttribute(k_layer_mma,
                         cudaFuncAttributeMaxDynamicSharedMemorySize,
                         (int)layer_smem);

    float* p_agg;
    cudaGetSymbolAddress((void**)&p_agg, g_agg);

    const int TPB = 256;
    int warp_blocks = (N_NODES * 32 + TPB - 1) / TPB;
    int oct_blocks = (N_NODES * 8 + TPB - 1) / TPB;    // 313
    int edge_blocks = (N_EDGES / 8 + TPB - 1) / TPB;   // 313

    k_prep<<<FILL_BLOCKS + CVT_BLOCKS + 1, TPB>>>(src, dst, x, Wself2, Wneigh2,
                                                  b2, Wpred);
    {
        void* args[] = {(void*)&x};
        launch_pdl((const void*)k_agg, dim3(warp_blocks), dim3(TPB), 0, args);
    }
    {
        void* args[] = {(void*)&x, (void*)&p_agg, (void*)&Wself1,
                        (void*)&Wneigh1, (void*)&b1};
        launch_pdl((const void*)k_layer_mma, dim3(GEMM_BLOCKS), dim3(TPB),
                   layer_smem, args);
    }
    {
        void* args[] = {};
        launch_pdl((const void*)k_agg2, dim3(oct_blocks), dim3(TPB), 0, args);
    }
    {
        void* args[] = {(void*)&src, (void*)&dst, (void*)&bpred, (void*)&out};
        launch_pdl((const void*)k_edge, dim3(edge_blocks), dim3(TPB), 0, args);
    }
}

// round 14
// speedup vs baseline: 1.1056x; 1.1056x over previous
#include <cuda_runtime.h>
#include <cuda_bf16.h>
#include <cstdint>

#define N_NODES 10000
#define N_EDGES 640000
#define D 128
#define CAP 160            // padded CSR bucket capacity (mean deg 64, sigma 8)
#define GEMM_BLOCKS 79     // ceil(10000/128)
#define NBLK 148
#define NTHR 1024
#define NWARP (NBLK * 32)  // 4736

// ---------------- scratch (device globals; no allocation allowed) ----------
__device__ float g_agg[N_NODES * D];
__device__ uint2 g_xh[N_NODES * 32];  // x in packed bf16
__device__ float4 g_vself[N_NODES];   // (A1 , A3) self terms
__device__ float4 g_vnb[N_NODES];     // (A2 , A4) neighbor terms
__device__ float2 g_ps[N_NODES];
__device__ float2 g_pd[N_NODES];
__device__ float g_wc[D * 8];         // [A1|A2|A3|A4] rows
__device__ float g_c[4];
__device__ int g_cnt[N_NODES];        // zeroed in k_tailedge (replay invariant)
__device__ int g_csr[N_NODES * CAP];
__device__ unsigned g_bar_a[2];       // self-resetting barriers (one per kernel)
__device__ unsigned g_bar_d[2];

// ---------------- helpers ---------------------------------------------------
__device__ __forceinline__ uint32_t f2tf32(float v) {
    uint32_t t;
    asm("cvt.rna.tf32.f32 %0, %1;" : "=r"(t) : "f"(v));
    return t;
}
__device__ __forceinline__ void mma_tf32(float* c, const uint32_t* a,
                                         uint32_t b0, uint32_t b1) {
    asm volatile(
        "mma.sync.aligned.m16n8k8.row.col.f32.tf32.tf32.f32 "
        "{%0,%1,%2,%3}, {%4,%5,%6,%7}, {%8,%9}, {%0,%1,%2,%3};"
        : "+f"(c[0]), "+f"(c[1]), "+f"(c[2]), "+f"(c[3])
        : "r"(a[0]), "r"(a[1]), "r"(a[2]), "r"(a[3]), "r"(b0), "r"(b1));
}

// grid barrier: all NBLK CTAs co-resident (148 blocks, 1 per SM, wave 1)
__device__ __forceinline__ void grid_sync(int i) {
    __syncthreads();
    if (threadIdx.x == 0) {
        __threadfence();
        unsigned a = atomicAdd(&g_bar_a[i], 1u) + 1u;
        if (a < NBLK) {
            while (*(volatile unsigned*)&g_bar_a[i] < NBLK) {}
        }
        __threadfence();
        unsigned dcnt = atomicAdd(&g_bar_d[i], 1u) + 1u;
        if (dcnt == NBLK) {
            g_bar_a[i] = 0u;
            __threadfence();
            g_bar_d[i] = 0u;
        }
    }
    __syncthreads();
}

// ======== kernel 1: prep (fill + cvt + wc) -> barrier -> agg ================
__global__ void __launch_bounds__(NTHR, 1)
k_prepagg(const int* __restrict__ src, const int* __restrict__ dst,
          const float* __restrict__ x,
          const float* __restrict__ Ws2, const float* __restrict__ Wn2,
          const float* __restrict__ b2, const float* __restrict__ Wp) {
    __shared__ float sWp[256 * 2];
    int bid = blockIdx.x;
    int tid = threadIdx.x;
    int widx = tid >> 5;
    int lane = tid & 31;
    int gw = bid * 32 + widx;

    // ---- phase A: CSR fill + bf16 cvt (blocks 0-146) | weight fold (147) --
    if (bid < NBLK - 1) {
        int tg = bid * NTHR + tid;
        const int NT0 = (NBLK - 1) * NTHR;   // 150528
        for (int t = tg; t < N_EDGES / 8; t += NT0) {
            int4 s0 = ((const int4*)src)[2 * t];
            int4 s1 = ((const int4*)src)[2 * t + 1];
            int4 d0 = ((const int4*)dst)[2 * t];
            int4 d1 = ((const int4*)dst)[2 * t + 1];
            int p0 = atomicAdd(&g_cnt[d0.x], 1);
            int p1 = atomicAdd(&g_cnt[d0.y], 1);
            int p2 = atomicAdd(&g_cnt[d0.z], 1);
            int p3 = atomicAdd(&g_cnt[d0.w], 1);
            int p4 = atomicAdd(&g_cnt[d1.x], 1);
            int p5 = atomicAdd(&g_cnt[d1.y], 1);
            int p6 = atomicAdd(&g_cnt[d1.z], 1);
            int p7 = atomicAdd(&g_cnt[d1.w], 1);
            if (p0 < CAP) g_csr[d0.x * CAP + p0] = s0.x;
            if (p1 < CAP) g_csr[d0.y * CAP + p1] = s0.y;
            if (p2 < CAP) g_csr[d0.z * CAP + p2] = s0.z;
            if (p3 < CAP) g_csr[d0.w * CAP + p3] = s0.w;
            if (p4 < CAP) g_csr[d1.x * CAP + p4] = s1.x;
            if (p5 < CAP) g_csr[d1.y * CAP + p5] = s1.y;
            if (p6 < CAP) g_csr[d1.z * CAP + p6] = s1.z;
            if (p7 < CAP) g_csr[d1.w * CAP + p7] = s1.w;
        }
        for (int i = tg; i < N_NODES * 16; i += NT0) {
            float4 a = ((const float4*)x)[2 * i];
            float4 b = ((const float4*)x)[2 * i + 1];
            __nv_bfloat162 q0 = __floats2bfloat162_rn(a.x, a.y);
            __nv_bfloat162 q1 = __floats2bfloat162_rn(a.z, a.w);
            __nv_bfloat162 q2 = __floats2bfloat162_rn(b.x, b.y);
            __nv_bfloat162 q3 = __floats2bfloat162_rn(b.z, b.w);
            uint4 u;
            u.x = *reinterpret_cast<unsigned*>(&q0);
            u.y = *reinterpret_cast<unsigned*>(&q1);
            u.z = *reinterpret_cast<unsigned*>(&q2);
            u.w = *reinterpret_cast<unsigned*>(&q3);
            ((uint4*)g_xh)[i] = u;
        }
    } else {
        for (int i = tid; i < 512; i += NTHR) sWp[i] = Wp[i];
        __syncthreads();
        if (tid < 128) {
            int t = tid;
            float a[8] = {0, 0, 0, 0, 0, 0, 0, 0};
#pragma unroll 4
            for (int j = 0; j < D; j++) {
                float ws = Ws2[t * D + j];
                float wn = Wn2[t * D + j];
                float p0 = sWp[j * 2], p1 = sWp[j * 2 + 1];
                float q0 = sWp[(128 + j) * 2], q1 = sWp[(128 + j) * 2 + 1];
                a[0] += ws * p0; a[1] += ws * p1;
                a[2] += wn * p0; a[3] += wn * p1;
                a[4] += ws * q0; a[5] += ws * q1;
                a[6] += wn * q0; a[7] += wn * q1;
            }
#pragma unroll
            for (int j = 0; j < 8; j++) g_wc[t * 8 + j] = a[j];
        }
        if (tid < 4) {
            int half = tid >> 1, c = tid & 1;
            float s = 0.f;
            for (int j = 0; j < D; j++)
                s += b2[j] * sWp[(half * 128 + j) * 2 + c];
            g_c[tid] = s;
        }
    }
    grid_sync(0);
    // prep outputs complete -> release k_layer_mma (overlaps agg phase below)
    cudaTriggerProgrammaticLaunchCompletion();

    // ---- phase B: pull-based mean aggregation over bf16 x -----------------
    for (int n = gw; n < N_NODES; n += NWARP) {
        int beg = n * CAP;
        int d = g_cnt[n];
        float ax = 0.f, ay = 0.f, az = 0.f, aw = 0.f;
        for (int base = 0; base < d; base += 32) {
            int my = -1;
            if (base + lane < d) my = g_csr[beg + base + lane];
            int cnt = min(32, d - base);
            int j = 0;
            for (; j + 8 <= cnt; j += 8) {
                int ss[8];
#pragma unroll
                for (int q = 0; q < 8; q++)
                    ss[q] = __shfl_sync(0xffffffffu, my, j + q);
                uint2 u[8];
#pragma unroll
                for (int q = 0; q < 8; q++) u[q] = g_xh[ss[q] * 32 + lane];
#pragma unroll
                for (int q = 0; q < 8; q++) {
                    float2 f;
                    f = __bfloat1622float2(
                        *reinterpret_cast<__nv_bfloat162*>(&u[q].x));
                    ax += f.x; ay += f.y;
                    f = __bfloat1622float2(
                        *reinterpret_cast<__nv_bfloat162*>(&u[q].y));
                    az += f.x; aw += f.y;
                }
            }
            for (; j < cnt; j++) {
                int s0 = __shfl_sync(0xffffffffu, my, j);
                uint2 u0 = g_xh[s0 * 32 + lane];
                float2 f;
                f = __bfloat1622float2(
                    *reinterpret_cast<__nv_bfloat162*>(&u0.x));
                ax += f.x; ay += f.y;
                f = __bfloat1622float2(
                    *reinterpret_cast<__nv_bfloat162*>(&u0.y));
                az += f.x; aw += f.y;
            }
        }
        float inv = 1.0f / (float)(d < 1 ? 1 : d);
        float4 r;
        r.x = ax * inv; r.y = ay * inv; r.z = az * inv; r.w = aw * inv;
        *(float4*)(g_agg + (size_t)n * D + lane * 4) = r;
    }
}

// ======== kernel 2: mma.sync tf32 layer 1 + fused projection ================
#define ASTR 132   // 128 + 4 pad (u32 units)

__global__ void __launch_bounds__(256, 1)
k_layer_mma(const float* __restrict__ x, const float* __restrict__ agg,
            const float* __restrict__ Wself, const float* __restrict__ Wneigh,
            const float* __restrict__ bias) {
    cudaTriggerProgrammaticLaunchCompletion();  // release k_tailedge early

    extern __shared__ uint32_t smu[];
    uint32_t* sA = smu;
    uint32_t* sB = smu + 128 * ASTR;
    float* sWc = (float*)(smu + 2 * 128 * ASTR);
    float* sBias = sWc + 1024;

    int tid = threadIdx.x;
    int wid = tid >> 5;
    int lane = tid & 31;
    int nb = blockIdx.x * 128;
    int valid = min(128, N_NODES - nb);

    // prologue: x, Wself, bias, wc — complete when the trigger fired
    for (int it = tid; it < 128 * 32; it += 256) {
        int r = it >> 5, q = it & 31;
        float4 vx = make_float4(0.f, 0.f, 0.f, 0.f);
        if (r < valid) vx = ((const float4*)x)[(size_t)(nb + r) * 32 + q];
        uint32_t* a = sA + r * ASTR + q * 4;
        a[0] = f2tf32(vx.x); a[1] = f2tf32(vx.y);
        a[2] = f2tf32(vx.z); a[3] = f2tf32(vx.w);
        float4 w = ((const float4*)Wself)[it];
        uint32_t* bp = sB + r * ASTR + q * 4;
        bp[0] = f2tf32(w.x); bp[1] = f2tf32(w.y);
        bp[2] = f2tf32(w.z); bp[3] = f2tf32(w.w);
    }
    for (int i = tid; i < D * 2; i += 256)
        ((float4*)sWc)[i] = ((const float4*)g_wc)[i];
    if (tid < 32) ((float4*)sBias)[tid] = ((const float4*)bias)[tid];
    __syncthreads();

    int wm = wid & 3, wn = wid >> 2;
    int tg8 = lane >> 2, tq = lane & 3;

    float c[2][8][4];
#pragma unroll
    for (int mi = 0; mi < 2; mi++)
#pragma unroll
        for (int ni = 0; ni < 8; ni++)
#pragma unroll
            for (int k = 0; k < 4; k++) c[mi][ni][k] = 0.f;

    // ---- pass 0: C = X @ Ws (overlaps agg phase of k_prepagg) ----
#pragma unroll 2
    for (int kc = 0; kc < 16; kc++) {
        int k0 = kc * 8;
        uint32_t a[2][4];
#pragma unroll
        for (int mi = 0; mi < 2; mi++) {
            int row = 32 * wm + 16 * mi + tg8;
            a[mi][0] = sA[row * ASTR + k0 + tq];
            a[mi][1] = sA[(row + 8) * ASTR + k0 + tq];
            a[mi][2] = sA[row * ASTR + k0 + tq + 4];
            a[mi][3] = sA[(row + 8) * ASTR + k0 + tq + 4];
        }
#pragma unroll
        for (int ni = 0; ni < 8; ni++) {
            int col = 64 * wn + 8 * ni + tg8;
            uint32_t b0 = sB[(k0 + tq) * ASTR + col];
            uint32_t b1r = sB[(k0 + tq + 4) * ASTR + col];
            mma_tf32(c[0][ni], a[0], b0, b1r);
            mma_tf32(c[1][ni], a[1], b0, b1r);
        }
    }
    __syncthreads();

    cudaGridDependencySynchronize();   // wait for k_prepagg (g_agg complete)

    // ---- load pass 1 tiles: A = agg rows, B = Wneigh ----
    for (int it = tid; it < 128 * 32; it += 256) {
        int r = it >> 5, q = it & 31;
        float4 vm = make_float4(0.f, 0.f, 0.f, 0.f);
        if (r < valid)
            vm = ((const float4*)agg)[(size_t)(nb + r) * 32 + q];
        uint32_t* a = sA + r * ASTR + q * 4;
        a[0] = f2tf32(vm.x); a[1] = f2tf32(vm.y);
        a[2] = f2tf32(vm.z); a[3] = f2tf32(vm.w);
        float4 w = ((const float4*)Wneigh)[it];
        uint32_t* bp = sB + r * ASTR + q * 4;
        bp[0] = f2tf32(w.x); bp[1] = f2tf32(w.y);
        bp[2] = f2tf32(w.z); bp[3] = f2tf32(w.w);
    }
    __syncthreads();

    // ---- pass 1: C += M @ Wn ----
#pragma unroll 2
    for (int kc = 0; kc < 16; kc++) {
        int k0 = kc * 8;
        uint32_t a[2][4];
#pragma unroll
        for (int mi = 0; mi < 2; mi++) {
            int row = 32 * wm + 16 * mi + tg8;
            a[mi][0] = sA[row * ASTR + k0 + tq];
            a[mi][1] = sA[(row + 8) * ASTR + k0 + tq];
            a[mi][2] = sA[row * ASTR + k0 + tq + 4];
            a[mi][3] = sA[(row + 8) * ASTR + k0 + tq + 4];
        }
#pragma unroll
        for (int ni = 0; ni < 8; ni++) {
            int col = 64 * wn + 8 * ni + tg8;
            uint32_t b0 = sB[(k0 + tq) * ASTR + col];
            uint32_t b1r = sB[(k0 + tq + 4) * ASTR + col];
            mma_tf32(c[0][ni], a[0], b0, b1r);
            mma_tf32(c[1][ni], a[1], b0, b1r);
        }
    }

    __syncthreads();
    float* sH = (float*)sA;
#pragma unroll
    for (int mi = 0; mi < 2; mi++) {
        int r0 = 32 * wm + 16 * mi + tg8;
#pragma unroll
        for (int ni = 0; ni < 8; ni++) {
            int cb = 64 * wn + 8 * ni + 2 * tq;
            sH[r0 * ASTR + cb] = fmaxf(c[mi][ni][0] + sBias[cb], 0.f);
            sH[r0 * ASTR + cb + 1] = fmaxf(c[mi][ni][1] + sBias[cb + 1], 0.f);
            sH[(r0 + 8) * ASTR + cb] = fmaxf(c[mi][ni][2] + sBias[cb], 0.f);
            sH[(r0 + 8) * ASTR + cb + 1] =
                fmaxf(c[mi][ni][3] + sBias[cb + 1], 0.f);
        }
    }
    __syncthreads();

    int node = tid >> 1;
    int half = tid & 1;
    float pv[8] = {0, 0, 0, 0, 0, 0, 0, 0};
    const float* hrow = sH + node * ASTR + half * 64;
#pragma unroll 8
    for (int j = 0; j < 64; j++) {
        float h = hrow[j];
        int col = half * 64 + j;
        float4 w0 = *(const float4*)(sWc + col * 8);
        float4 w1 = *(const float4*)(sWc + col * 8 + 4);
        pv[0] += h * w0.x; pv[1] += h * w0.y;
        pv[2] += h * w0.z; pv[3] += h * w0.w;
        pv[4] += h * w1.x; pv[5] += h * w1.y;
        pv[6] += h * w1.z; pv[7] += h * w1.w;
    }
#pragma unroll
    for (int m = 0; m < 8; m++)
        pv[m] += __shfl_xor_sync(0xffffffffu, pv[m], 1);
    int gn = nb + node;
    if (half == 0 && gn < N_NODES) {
        g_vself[gn] = make_float4(pv[0], pv[1], pv[4], pv[5]);
        g_vnb[gn] = make_float4(pv[2], pv[3], pv[6], pv[7]);
    }
}

// ======== kernel 3: tiny aggregation -> barrier -> edge scores ==============
// Preloads (CSR idx, edge ids, consts) all come from k_prepagg outputs,
// which are transitively complete -> issued BEFORE the PDL sync to overlap
// k_layer_mma.
__global__ void __launch_bounds__(NTHR, 1)
k_tailedge(const int* __restrict__ src, const int* __restrict__ dst,
           const float* __restrict__ bpred, float* __restrict__ out) {
    int bid = blockIdx.x;
    int tid = threadIdx.x;
    int lane = tid & 31;
    int gw = bid * 32 + (tid >> 5);
    int gid = bid * NTHR + tid;

    // preload for agg2 phase (8 lanes/node, 4 nodes/warp; single pass)
    int sub = lane & 7;
    int n = gw * 4 + (lane >> 3);          // 0..18943
    int d = 0, beg = 0;
    if (n < N_NODES) {
        d = g_cnt[n];
        beg = n * CAP;
    }
    int idx[8];
#pragma unroll
    for (int i = 0; i < 8; i++)
        idx[i] = (sub + 8 * i < d) ? g_csr[beg + sub + 8 * i] : -1;

    // preload for edge phase (one 8-edge group per thread)
    int4 es0 = make_int4(0, 0, 0, 0), es1 = es0, ed0 = es0, ed1 = es0;
    bool has_edge = gid < N_EDGES / 8;
    if (has_edge) {
        es0 = ((const int4*)src)[2 * gid];
        es1 = ((const int4*)src)[2 * gid + 1];
        ed0 = ((const int4*)dst)[2 * gid];
        ed1 = ((const int4*)dst)[2 * gid + 1];
    }
    float b0 = __ldg(bpred) + g_c[0] + g_c[2];
    float b1v = __ldg(bpred + 1) + g_c[1] + g_c[3];

    cudaGridDependencySynchronize();   // wait k_layer_mma (g_vnb/g_vself)

    // ---- agg2: gather projected neighbor terms, reduce over 8 lanes -------
    {
        float ax = 0.f, ay = 0.f, az = 0.f, aw = 0.f;
#pragma unroll
        for (int i = 0; i < 8; i++) {
            if (idx[i] >= 0) {
                float4 v = g_vnb[idx[i]];
                ax += v.x; ay += v.y; az += v.z; aw += v.w;
            }
        }
        for (int i = 64 + sub; i < d; i += 8) {   // rare tail (deg > 64)
            int s = g_csr[beg + i];
            float4 v = g_vnb[s];
            ax += v.x; ay += v.y; az += v.z; aw += v.w;
        }
#pragma unroll
        for (int off = 4; off > 0; off >>= 1) {
            ax += __shfl_xor_sync(0xffffffffu, ax, off);
            ay += __shfl_xor_sync(0xffffffffu, ay, off);
            az += __shfl_xor_sync(0xffffffffu, az, off);
            aw += __shfl_xor_sync(0xffffffffu, aw, off);
        }
        if (sub == 0 && n < N_NODES) {
            float inv = 1.0f / (float)(d < 1 ? 1 : d);
            float4 vs = g_vself[n];
            g_ps[n] = make_float2(vs.x + ax * inv, vs.y + ay * inv);
            g_pd[n] = make_float2(vs.z + az * inv, vs.w + aw * inv);
            g_cnt[n] = 0;   // restore invariant for next graph replay
        }
    }

    grid_sync(1);

    // ---- edge scores -------------------------------------------------------
    if (has_edge) {
        int t = gid;
        float2 a0 = g_ps[es0.x], a1 = g_ps[es0.y];
        float2 a2 = g_ps[es0.z], a3 = g_ps[es0.w];
        float2 a4 = g_ps[es1.x], a5 = g_ps[es1.y];
        float2 a6 = g_ps[es1.z], a7 = g_ps[es1.w];
        float2 c0 = g_pd[ed0.x], c1 = g_pd[ed0.y];
        float2 c2 = g_pd[ed0.z], c3 = g_pd[ed0.w];
        float2 c4 = g_pd[ed1.x], c5 = g_pd[ed1.y];
        float2 c6 = g_pd[ed1.z], c7 = g_pd[ed1.w];
        float4 o;
        o = make_float4(a0.x + c0.x + b0, a0.y + c0.y + b1v,
                        a1.x + c1.x + b0, a1.y + c1.y + b1v);
        ((float4*)out)[t * 4] = o;
        o = make_float4(a2.x + c2.x + b0, a2.y + c2.y + b1v,
                        a3.x + c3.x + b0, a3.y + c3.y + b1v);
        ((float4*)out)[t * 4 + 1] = o;
        o = make_float4(a4.x + c4.x + b0, a4.y + c4.y + b1v,
                        a5.x + c5.x + b0, a5.y + c5.y + b1v);
        ((float4*)out)[t * 4 + 2] = o;
        o = make_float4(a6.x + c6.x + b0, a6.y + c6.y + b1v,
                        a7.x + c7.x + b0, a7.y + c7.y + b1v);
        ((float4*)out)[t * 4 + 3] = o;
    }
}

// ---------------- launcher (3 kernels, PDL-chained) -------------------------
static void launch_pdl(const void* func, dim3 grid, dim3 block, size_t smem,
                       void** args) {
    cudaLaunchConfig_t cfg = {};
    cfg.gridDim = grid;
    cfg.blockDim = block;
    cfg.dynamicSmemBytes = smem;
    cfg.stream = 0;
    cudaLaunchAttribute attr;
    attr.id = cudaLaunchAttributeProgrammaticStreamSerialization;
    attr.val.programmaticStreamSerializationAllowed = 1;
    cfg.attrs = &attr;
    cfg.numAttrs = 1;
    cudaLaunchKernelExC(&cfg, func, args);
}

extern "C" void kernel_launch(void* const* d_in, const int* in_sizes, int n_in,
                              void* d_out, int out_size) {
    const float* x = (const float*)d_in[0];
    const int* src = (const int*)d_in[1];
    const int* dst = (const int*)d_in[2];
    const float* Wself1 = (const float*)d_in[3];
    const float* Wneigh1 = (const float*)d_in[4];
    const float* b1 = (const float*)d_in[5];
    const float* Wself2 = (const float*)d_in[6];
    const float* Wneigh2 = (const float*)d_in[7];
    const float* b2 = (const float*)d_in[8];
    const float* Wpred = (const float*)d_in[9];
    const float* bpred = (const float*)d_in[10];
    float* out = (float*)d_out;

    size_t layer_smem = (size_t)(2 * 128 * ASTR + 1024 + 128) * 4;
    cudaFuncSetAttribute(k_layer_mma,
                         cudaFuncAttributeMaxDynamicSharedMemorySize,
                         (int)layer_smem);

    float* p_agg;
    cudaGetSymbolAddress((void**)&p_agg, g_agg);

    k_prepagg<<<NBLK, NTHR>>>(src, dst, x, Wself2, Wneigh2, b2, Wpred);
    {
        void* args[] = {(void*)&x, (void*)&p_agg, (void*)&Wself1,
                        (void*)&Wneigh1, (void*)&b1};
        launch_pdl((const void*)k_layer_mma, dim3(GEMM_BLOCKS), dim3(256),
                   layer_smem, args);
    }
    {
        void* args[] = {(void*)&src, (void*)&dst, (void*)&bpred, (void*)&out};
        launch_pdl((const void*)k_tailedge, dim3(NBLK), dim3(NTHR), 0, args);
    }
}